// round 4
// baseline (speedup 1.0000x reference)
#include <cuda_runtime.h>
#include <cuda_bf16.h>

#define N_USER  50000
#define N_ITEM  100000
#define N_NODES 150000
#define DD      64
#define NLAYER  3
#define NNZ     2400000
#define BB      1024
#define NB_SCAN 587   // ceil(N_NODES/256)
#define WPITCH  132   // padded k-pitch for transposed W (conflict-free reads)
#define RPITCH  68    // smem row pitch (floats) for LE/E tiles
#define SMEM_BYTES ((2 * 128 * RPITCH + 64 * WPITCH + 64) * 4)

// Scratch (device globals: allocation-free per harness rules)
__device__ float4 g_E [N_NODES * 16];   // E ping  [N,64]
__device__ float4 g_E2[N_NODES * 16];   // E pong  [N,64]
__device__ float  g_mlp[BB * DD];
__device__ int    g_win[N_USER];
// CSR scratch
__device__ int    g_cnt[N_NODES];
__device__ int    g_ptr[N_NODES];
__device__ int    g_cur[N_NODES];
__device__ int    g_bsum[NB_SCAN];
__device__ int    g_bscan[NB_SCAN];
__device__ int2   g_cv[NNZ];            // {col, float_as_int(val)}
// tf32-split transposed weights: [layer][n(64)][k padded to 132]
__device__ unsigned int g_whiT[NLAYER * 64 * WPITCH];
__device__ unsigned int g_wloT[NLAYER * 64 * WPITCH];

// ---------------- tiny MLP ----------------
__global__ void k_mlp(const float* __restrict__ feat,
                      const float* __restrict__ l1w, const float* __restrict__ l1b,
                      const float* __restrict__ l2w, const float* __restrict__ l2b) {
    __shared__ float h[32];
    int i = blockIdx.x, t = threadIdx.x;
    if (t < 32) {
        float s = l1b[t];
#pragma unroll
        for (int f = 0; f < 4; f++) s += feat[i * 4 + f] * l1w[f * 32 + t];
        h[t] = s;
    }
    __syncthreads();
    float s = l2b[t];
#pragma unroll
    for (int j = 0; j < 32; j++) s += h[j] * l2w[j * DD + t];
    g_mlp[i * DD + t] = s;
}

// ---------------- E = concat(user_emb, item_emb) ----------------
__global__ void k_init(const float4* __restrict__ ue, const float4* __restrict__ ie) {
    int i = blockIdx.x * blockDim.x + threadIdx.x;
    const int NU4 = N_USER * 16;
    if (i < NU4) g_E[i] = ue[i];
    else if (i < N_NODES * 16) g_E[i] = ie[i - NU4];
}

// ---------------- last-wins scatter of user updates ----------------
__global__ void k_win_reset(const int* __restrict__ ui) {
    int i = blockIdx.x * blockDim.x + threadIdx.x;
    if (i < BB) g_win[ui[i]] = -1;
}
__global__ void k_win_max(const int* __restrict__ ui) {
    int i = blockIdx.x * blockDim.x + threadIdx.x;
    if (i < BB) atomicMax(&g_win[ui[i]], i);
}
__global__ void k_apply(const int* __restrict__ ui, const float* __restrict__ user_emb,
                        const float* __restrict__ ratio) {
    int i = blockIdx.x, t = threadIdx.x;  // 64 threads
    int u = ui[i];
    if (g_win[u] != i) return;
    float r = *ratio;
    float* E = (float*)g_E;
    E[u * DD + t] = user_emb[u * DD + t] * (1.0f - r) + g_mlp[i * DD + t] * r;
}

// ================= CSR build =================
__global__ void k_cnt_zero() {
    int i = blockIdx.x * blockDim.x + threadIdx.x;
    if (i < N_NODES) g_cnt[i] = 0;
}
__global__ void k_hist(const int* __restrict__ row) {
    int e = blockIdx.x * blockDim.x + threadIdx.x;
    if (e < NNZ) atomicAdd(&g_cnt[row[e]], 1);
}
__global__ void k_scan1() {
    __shared__ int s[256];
    int t = threadIdx.x;
    int i = blockIdx.x * 256 + t;
    int v = (i < N_NODES) ? g_cnt[i] : 0;
    s[t] = v;
    __syncthreads();
#pragma unroll
    for (int off = 1; off < 256; off <<= 1) {
        int u = (t >= off) ? s[t - off] : 0;
        __syncthreads();
        s[t] += u;
        __syncthreads();
    }
    if (i < N_NODES) g_ptr[i] = s[t] - v;
    if (t == 255) g_bsum[blockIdx.x] = s[255];
}
__global__ void k_scan2() {
    __shared__ int s[1024];
    int t = threadIdx.x;
    int v = (t < NB_SCAN) ? g_bsum[t] : 0;
    s[t] = v;
    __syncthreads();
#pragma unroll
    for (int off = 1; off < 1024; off <<= 1) {
        int u = (t >= off) ? s[t - off] : 0;
        __syncthreads();
        s[t] += u;
        __syncthreads();
    }
    if (t < NB_SCAN) g_bscan[t] = s[t] - v;
}
__global__ void k_scan3() {
    int i = blockIdx.x * blockDim.x + threadIdx.x;
    if (i < N_NODES) {
        int p = g_ptr[i] + g_bscan[i >> 8];
        g_ptr[i] = p;
        g_cur[i] = p;
    }
}
__global__ void k_fill(const int* __restrict__ row, const int* __restrict__ col,
                       const float* __restrict__ val) {
    int e = blockIdx.x * blockDim.x + threadIdx.x;
    if (e >= NNZ) return;
    int r = row[e];
    int pos = atomicAdd(&g_cur[r], 1);
    g_cv[pos] = make_int2(col[e], __float_as_int(val[e]));
}

// ================= W split (hi/lo tf32), transposed + padded =================
__global__ void k_wsplit(const float* __restrict__ w1, const float* __restrict__ w2) {
    int idx = blockIdx.x * 256 + threadIdx.x;  // over NLAYER*64*128
    if (idx >= NLAYER * 64 * 128) return;
    int layer = idx / (64 * 128);
    int rem = idx % (64 * 128);
    int n = rem / 128, k = rem % 128;
    float w = (k < 64) ? w1[layer * 4096 + k * 64 + n]
                       : w2[layer * 4096 + (k - 64) * 64 + n];
    unsigned int hi;
    asm("cvt.rna.tf32.f32 %0, %1;" : "=r"(hi) : "f"(w));
    float lof = w - __uint_as_float(hi);
    unsigned int lo;
    asm("cvt.rna.tf32.f32 %0, %1;" : "=r"(lo) : "f"(lof));
    g_whiT[layer * 64 * WPITCH + n * WPITCH + k] = hi;
    g_wloT[layer * 64 * WPITCH + n * WPITCH + k] = lo;
}

// ================= fused layer: spmm (-> smem) + 3xTF32 mma + bias + leaky ====
#define MMA_TF32(C, A0, A1, A2, A3, B0, B1)                                      \
    asm volatile("mma.sync.aligned.m16n8k8.row.col.f32.tf32.tf32.f32 "           \
                 "{%0,%1,%2,%3}, {%4,%5,%6,%7}, {%8,%9}, {%0,%1,%2,%3};"         \
                 : "+f"(C[0]), "+f"(C[1]), "+f"(C[2]), "+f"(C[3])                \
                 : "r"(A0), "r"(A1), "r"(A2), "r"(A3), "r"(B0), "r"(B1))

__global__ void __launch_bounds__(256) k_layer(int layer, int in_parity,
                                               const float* __restrict__ b1,
                                               const float* __restrict__ b2) {
    extern __shared__ float smem[];
    float*        sLE = smem;                              // 128 * RPITCH
    float*        sE  = smem + 128 * RPITCH;               // 128 * RPITCH
    unsigned int* whi = (unsigned int*)(smem + 2 * 128 * RPITCH);  // 64 * WPITCH
    float*        bs  = (float*)(whi + 64 * WPITCH);       // 64

    int t = threadIdx.x;
    int warp = t >> 5, lane = t & 31;
    const float*  Ein  = in_parity ? (const float*)g_E2 : (const float*)g_E;
    float*        Eout = in_parity ? (float*)g_E        : (float*)g_E2;

    // --- cooperative loads: weights-hi, bias, block's E rows ---
    {
        const uint4* s4 = (const uint4*)(g_whiT + layer * 64 * WPITCH);
        uint4* d4 = (uint4*)whi;
        for (int i = t; i < 64 * WPITCH / 4; i += 256) d4[i] = s4[i];
        if (t < 64) bs[t] = b1[t] + b2[t];
        const float4* Eg4 = (const float4*)Ein;
        for (int i = t; i < 128 * 16; i += 256) {
            int row = i >> 4, q4 = i & 15;
            int grow = blockIdx.x * 128 + row;
            int gc = min(grow, N_NODES - 1);
            *(float4*)&sE[row * RPITCH + q4 * 4] = Eg4[gc * 16 + q4];
        }
    }

    // --- phase 1: CSR spmm, 16 rows per warp, result rows into sLE ---
    {
        const float2* __restrict__ E2 = (const float2*)Ein;
        for (int rr = 0; rr < 16; rr++) {
            int row = blockIdx.x * 128 + warp * 16 + rr;
            float2 a0 = make_float2(0.f, 0.f), a1 = make_float2(0.f, 0.f);
            float2 a2 = make_float2(0.f, 0.f), a3 = make_float2(0.f, 0.f);
            if (row < N_NODES) {
                int start = g_ptr[row];
                int end = start + g_cnt[row];
                int e = start;
                for (; e + 4 <= end; e += 4) {
                    int2 cv0 = g_cv[e],     cv1 = g_cv[e + 1];
                    int2 cv2 = g_cv[e + 2], cv3 = g_cv[e + 3];
                    float2 x0 = E2[cv0.x * 32 + lane];
                    float2 x1 = E2[cv1.x * 32 + lane];
                    float2 x2 = E2[cv2.x * 32 + lane];
                    float2 x3 = E2[cv3.x * 32 + lane];
                    float v0 = __int_as_float(cv0.y), v1 = __int_as_float(cv1.y);
                    float v2 = __int_as_float(cv2.y), v3 = __int_as_float(cv3.y);
                    a0.x += v0 * x0.x; a0.y += v0 * x0.y;
                    a1.x += v1 * x1.x; a1.y += v1 * x1.y;
                    a2.x += v2 * x2.x; a2.y += v2 * x2.y;
                    a3.x += v3 * x3.x; a3.y += v3 * x3.y;
                }
                for (; e < end; e++) {
                    int2 cv = g_cv[e];
                    float2 x = E2[cv.x * 32 + lane];
                    float v = __int_as_float(cv.y);
                    a0.x += v * x.x; a0.y += v * x.y;
                }
            }
            a0.x += a1.x + a2.x + a3.x;
            a0.y += a1.y + a2.y + a3.y;
            *(float2*)&sLE[(warp * 16 + rr) * RPITCH + 2 * lane] = a0;
        }
    }
    __syncthreads();

    // --- phase 2: C[128x64] = [LE+E | LE*E] @ [w1;w2] via m16n8k8 tf32 ---
    int q = lane & 3, g = lane >> 2;
    int l0 = warp * 16 + g, l1 = l0 + 8;
    int r0 = blockIdx.x * 128 + l0, r1 = r0 + 8;
    const unsigned int* __restrict__ wlo = g_wloT + layer * 64 * WPITCH;

    float C[8][4];
#pragma unroll
    for (int i = 0; i < 8; i++)
#pragma unroll
        for (int j = 0; j < 4; j++) C[i][j] = 0.f;

#pragma unroll
    for (int kk = 0; kk < 16; kk++) {
        int half = kk >> 3;            // 0: (LE+E), 1: (LE*E)
        int cb = (kk & 7) * 8;
        int c0 = cb + q, c1 = cb + q + 4;
        float l00 = sLE[l0 * RPITCH + c0], e00 = sE[l0 * RPITCH + c0];
        float l10 = sLE[l1 * RPITCH + c0], e10 = sE[l1 * RPITCH + c0];
        float l01 = sLE[l0 * RPITCH + c1], e01 = sE[l0 * RPITCH + c1];
        float l11 = sLE[l1 * RPITCH + c1], e11 = sE[l1 * RPITCH + c1];
        float x0 = half ? l00 * e00 : l00 + e00;
        float x1 = half ? l10 * e10 : l10 + e10;
        float x2 = half ? l01 * e01 : l01 + e01;
        float x3 = half ? l11 * e11 : l11 + e11;
        unsigned int ah0, ah1, ah2, ah3, al0, al1, al2, al3;
        asm("cvt.rna.tf32.f32 %0, %1;" : "=r"(ah0) : "f"(x0));
        asm("cvt.rna.tf32.f32 %0, %1;" : "=r"(ah1) : "f"(x1));
        asm("cvt.rna.tf32.f32 %0, %1;" : "=r"(ah2) : "f"(x2));
        asm("cvt.rna.tf32.f32 %0, %1;" : "=r"(ah3) : "f"(x3));
        float y0 = x0 - __uint_as_float(ah0);
        float y1 = x1 - __uint_as_float(ah1);
        float y2 = x2 - __uint_as_float(ah2);
        float y3 = x3 - __uint_as_float(ah3);
        asm("cvt.rna.tf32.f32 %0, %1;" : "=r"(al0) : "f"(y0));
        asm("cvt.rna.tf32.f32 %0, %1;" : "=r"(al1) : "f"(y1));
        asm("cvt.rna.tf32.f32 %0, %1;" : "=r"(al2) : "f"(y2));
        asm("cvt.rna.tf32.f32 %0, %1;" : "=r"(al3) : "f"(y3));
        int krow = kk * 8 + q;
#pragma unroll
        for (int nt = 0; nt < 8; nt++) {
            int wb = (nt * 8 + g) * WPITCH + krow;
            unsigned int bh0 = whi[wb], bh1 = whi[wb + 4];
            unsigned int bl0 = __ldg(&wlo[wb]), bl1 = __ldg(&wlo[wb + 4]);
            MMA_TF32(C[nt], ah0, ah1, ah2, ah3, bh0, bh1);
            MMA_TF32(C[nt], al0, al1, al2, al3, bh0, bh1);
            MMA_TF32(C[nt], ah0, ah1, ah2, ah3, bl0, bl1);
        }
    }

#pragma unroll
    for (int nt = 0; nt < 8; nt++) {
        int col = nt * 8 + 2 * q;
        float b0v = bs[col], b1v = bs[col + 1];
        float v00 = C[nt][0] + b0v, v01 = C[nt][1] + b1v;
        float v10 = C[nt][2] + b0v, v11 = C[nt][3] + b1v;
        v00 = v00 >= 0.f ? v00 : 0.2f * v00;
        v01 = v01 >= 0.f ? v01 : 0.2f * v01;
        v10 = v10 >= 0.f ? v10 : 0.2f * v10;
        v11 = v11 >= 0.f ? v11 : 0.2f * v11;
        if (r0 < N_NODES) *(float2*)(Eout + r0 * 64 + col) = make_float2(v00, v01);
        if (r1 < N_NODES) *(float2*)(Eout + r1 * 64 + col) = make_float2(v10, v11);
    }
}

// ---------------- gather (with optional row-normalize) into output ----------------
__global__ void k_gather(const int* __restrict__ user_idx, const int* __restrict__ pos_idx,
                         const int* __restrict__ neg_idx, float* __restrict__ out,
                         int layer, int parity) {
    int w = (blockIdx.x * blockDim.x + threadIdx.x) >> 5;
    int lane = threadIdx.x & 31;
    if (w >= 3 * BB) return;
    int node;
    if (w < BB)          node = user_idx[w];
    else if (w < 2 * BB) node = N_USER + pos_idx[w - BB];
    else                 node = N_USER + neg_idx[w - 2 * BB];
    const float2* Ebuf = parity ? (const float2*)g_E2 : (const float2*)g_E;
    float2 v = Ebuf[node * 32 + lane];
    float scale = 1.0f;
    if (layer > 0) {
        float s = v.x * v.x + v.y * v.y;
#pragma unroll
        for (int o = 16; o; o >>= 1) s += __shfl_xor_sync(0xffffffffu, s, o);
        scale = 1.0f / fmaxf(sqrtf(s), 1e-12f);
    }
    ((float2*)(out + (size_t)w * 256 + layer * 64))[lane] = make_float2(v.x * scale, v.y * scale);
}

extern "C" void kernel_launch(void* const* d_in, const int* in_sizes, int n_in,
                              void* d_out, int out_size) {
    const float *user_emb, *item_emb, *lin1_w, *lin1_b, *lin2_w, *lin2_b;
    const float *w1, *b1, *w2, *b2, *lap_val, *user_feat, *mlp_ratio;
    const int *lap_row, *lap_col, *user_idx, *pos_idx, *neg_idx;

    if (in_sizes[2] == 4096) {
        user_emb = (const float*)d_in[0];  item_emb = (const float*)d_in[1];
        user_feat= (const float*)d_in[2];
        lin1_w   = (const float*)d_in[3];  lin1_b   = (const float*)d_in[4];
        lin2_w   = (const float*)d_in[5];  lin2_b   = (const float*)d_in[6];
        w1 = (const float*)d_in[7];  b1 = (const float*)d_in[8];
        w2 = (const float*)d_in[9];  b2 = (const float*)d_in[10];
        lap_val  = (const float*)d_in[11]; mlp_ratio = (const float*)d_in[12];
        lap_row  = (const int*)d_in[13];   lap_col   = (const int*)d_in[14];
        user_idx = (const int*)d_in[15];   pos_idx   = (const int*)d_in[16];
        neg_idx  = (const int*)d_in[17];
    } else {
        user_emb = (const float*)d_in[0];  item_emb = (const float*)d_in[1];
        lin1_w   = (const float*)d_in[2];  lin1_b   = (const float*)d_in[3];
        lin2_w   = (const float*)d_in[4];  lin2_b   = (const float*)d_in[5];
        w1 = (const float*)d_in[6];  b1 = (const float*)d_in[7];
        w2 = (const float*)d_in[8];  b2 = (const float*)d_in[9];
        lap_row  = (const int*)d_in[10];   lap_col  = (const int*)d_in[11];
        lap_val  = (const float*)d_in[12];
        user_idx = (const int*)d_in[13];   user_feat = (const float*)d_in[14];
        pos_idx  = (const int*)d_in[15];   neg_idx   = (const int*)d_in[16];
        mlp_ratio= (const float*)d_in[17];
    }

    float* out = (float*)d_out;
    const int V4 = N_NODES * 16;

    // raise dynamic smem limit for the fused layer kernel (idempotent)
    cudaFuncSetAttribute(k_layer, cudaFuncAttributeMaxDynamicSharedMemorySize, SMEM_BYTES);

    // CSR build + weight split (independent of E; do them first)
    k_cnt_zero<<<NB_SCAN, 256>>>();
    k_hist<<<(NNZ + 255) / 256, 256>>>(lap_row);
    k_scan1<<<NB_SCAN, 256>>>();
    k_scan2<<<1, 1024>>>();
    k_scan3<<<NB_SCAN, 256>>>();
    k_fill<<<(NNZ + 255) / 256, 256>>>(lap_row, lap_col, lap_val);
    k_wsplit<<<(NLAYER * 64 * 128 + 255) / 256, 256>>>(w1, w2);

    k_mlp<<<BB, 64>>>(user_feat, lin1_w, lin1_b, lin2_w, lin2_b);
    k_init<<<(V4 + 255) / 256, 256>>>((const float4*)user_emb, (const float4*)item_emb);
    k_win_reset<<<(BB + 255) / 256, 256>>>(user_idx);
    k_win_max<<<(BB + 255) / 256, 256>>>(user_idx);
    k_apply<<<BB, 64>>>(user_idx, user_emb, mlp_ratio);
    k_gather<<<(3 * BB * 32 + 255) / 256, 256>>>(user_idx, pos_idx, neg_idx, out, 0, 0);

    for (int k = 0; k < NLAYER; k++) {
        int in_par = k & 1;                 // 0:g_E, 1:g_E2
        k_layer<<<(N_NODES + 127) / 128, 256, SMEM_BYTES>>>(k, in_par, b1 + k * 64, b2 + k * 64);
        k_gather<<<(3 * BB * 32 + 255) / 256, 256>>>(user_idx, pos_idx, neg_idx, out,
                                                     k + 1, (k + 1) & 1);
    }
}

// round 5
// speedup vs baseline: 2.5490x; 2.5490x over previous
#include <cuda_runtime.h>
#include <cuda_bf16.h>

#define N_USER  50000
#define N_ITEM  100000
#define N_NODES 150000
#define DD      64
#define NLAYER  3
#define NNZ     2400000
#define BB      1024
#define NB_SCAN 587   // ceil(N_NODES/256)
#define WPITCH  132   // padded k-pitch for transposed W (conflict-free LDS)

// Scratch (device globals: allocation-free per harness rules)
__device__ float4 g_E [N_NODES * 16];   // E  [N,64] as float4
__device__ float4 g_LE[N_NODES * 16];   // L_E[N,64] as float4
__device__ float  g_mlp[BB * DD];
__device__ int    g_win[N_USER];
// CSR scratch
__device__ int    g_cnt[N_NODES];
__device__ int    g_ptr[N_NODES];
__device__ int    g_cur[N_NODES];
__device__ int    g_bsum[NB_SCAN];
__device__ int    g_bscan[NB_SCAN];
__device__ int2   g_cv[NNZ];            // {col, float_as_int(val)}
// tf32-split transposed weights: [layer][n(64)][k padded to 132]
__device__ unsigned int g_whiT[NLAYER * 64 * WPITCH];
__device__ unsigned int g_wloT[NLAYER * 64 * WPITCH];

// ---------------- tiny MLP ----------------
__global__ void k_mlp(const float* __restrict__ feat,
                      const float* __restrict__ l1w, const float* __restrict__ l1b,
                      const float* __restrict__ l2w, const float* __restrict__ l2b) {
    __shared__ float h[32];
    int i = blockIdx.x, t = threadIdx.x;
    if (t < 32) {
        float s = l1b[t];
#pragma unroll
        for (int f = 0; f < 4; f++) s += feat[i * 4 + f] * l1w[f * 32 + t];
        h[t] = s;
    }
    __syncthreads();
    float s = l2b[t];
#pragma unroll
    for (int j = 0; j < 32; j++) s += h[j] * l2w[j * DD + t];
    g_mlp[i * DD + t] = s;
}

// ---------------- E = concat(user_emb, item_emb) ----------------
__global__ void k_init(const float4* __restrict__ ue, const float4* __restrict__ ie) {
    int i = blockIdx.x * blockDim.x + threadIdx.x;
    const int NU4 = N_USER * 16;
    if (i < NU4) g_E[i] = ue[i];
    else if (i < N_NODES * 16) g_E[i] = ie[i - NU4];
}

// ---------------- last-wins scatter of user updates ----------------
__global__ void k_win_reset(const int* __restrict__ ui) {
    int i = blockIdx.x * blockDim.x + threadIdx.x;
    if (i < BB) g_win[ui[i]] = -1;
}
__global__ void k_win_max(const int* __restrict__ ui) {
    int i = blockIdx.x * blockDim.x + threadIdx.x;
    if (i < BB) atomicMax(&g_win[ui[i]], i);
}
__global__ void k_apply(const int* __restrict__ ui, const float* __restrict__ user_emb,
                        const float* __restrict__ ratio) {
    int i = blockIdx.x, t = threadIdx.x;  // 64 threads
    int u = ui[i];
    if (g_win[u] != i) return;
    float r = *ratio;
    float* E = (float*)g_E;
    E[u * DD + t] = user_emb[u * DD + t] * (1.0f - r) + g_mlp[i * DD + t] * r;
}

// ================= CSR build =================
__global__ void k_cnt_zero() {
    int i = blockIdx.x * blockDim.x + threadIdx.x;
    if (i < N_NODES) g_cnt[i] = 0;
}
__global__ void k_hist(const int* __restrict__ row) {
    int e = blockIdx.x * blockDim.x + threadIdx.x;
    if (e < NNZ) atomicAdd(&g_cnt[row[e]], 1);
}
__global__ void k_scan1() {
    __shared__ int s[256];
    int t = threadIdx.x;
    int i = blockIdx.x * 256 + t;
    int v = (i < N_NODES) ? g_cnt[i] : 0;
    s[t] = v;
    __syncthreads();
#pragma unroll
    for (int off = 1; off < 256; off <<= 1) {
        int u = (t >= off) ? s[t - off] : 0;
        __syncthreads();
        s[t] += u;
        __syncthreads();
    }
    if (i < N_NODES) g_ptr[i] = s[t] - v;
    if (t == 255) g_bsum[blockIdx.x] = s[255];
}
__global__ void k_scan2() {
    __shared__ int s[1024];
    int t = threadIdx.x;
    int v = (t < NB_SCAN) ? g_bsum[t] : 0;
    s[t] = v;
    __syncthreads();
#pragma unroll
    for (int off = 1; off < 1024; off <<= 1) {
        int u = (t >= off) ? s[t - off] : 0;
        __syncthreads();
        s[t] += u;
        __syncthreads();
    }
    if (t < NB_SCAN) g_bscan[t] = s[t] - v;
}
__global__ void k_scan3() {
    int i = blockIdx.x * blockDim.x + threadIdx.x;
    if (i < N_NODES) {
        int p = g_ptr[i] + g_bscan[i >> 8];
        g_ptr[i] = p;
        g_cur[i] = p;
    }
}
__global__ void k_fill(const int* __restrict__ row, const int* __restrict__ col,
                       const float* __restrict__ val) {
    int e = blockIdx.x * blockDim.x + threadIdx.x;
    if (e >= NNZ) return;
    int r = row[e];
    int pos = atomicAdd(&g_cur[r], 1);
    g_cv[pos] = make_int2(col[e], __float_as_int(val[e]));
}

// ================= CSR SpMM: 2 rows per warp, 16 lanes x float4 per row =======
__global__ void __launch_bounds__(256) k_spmm_csr() {
    int w = (blockIdx.x * blockDim.x + threadIdx.x) >> 5;
    int lane = threadIdx.x & 31;
    int half = lane >> 4;       // 0 or 1: which row this half-warp owns
    int hl = lane & 15;         // lane within half (float4 slot)
    int row = w * 2 + half;
    if (row >= N_NODES) return;
    int start = g_ptr[row];
    int end = start + g_cnt[row];
    const float4* __restrict__ E4 = (const float4*)g_E;

    float4 a0 = make_float4(0.f, 0.f, 0.f, 0.f);
    float4 a1 = make_float4(0.f, 0.f, 0.f, 0.f);
    float4 a2 = make_float4(0.f, 0.f, 0.f, 0.f);
    float4 a3 = make_float4(0.f, 0.f, 0.f, 0.f);
    int e = start;
    for (; e + 4 <= end; e += 4) {
        int2 cv0 = g_cv[e],     cv1 = g_cv[e + 1];
        int2 cv2 = g_cv[e + 2], cv3 = g_cv[e + 3];
        float4 x0 = E4[cv0.x * 16 + hl];
        float4 x1 = E4[cv1.x * 16 + hl];
        float4 x2 = E4[cv2.x * 16 + hl];
        float4 x3 = E4[cv3.x * 16 + hl];
        float v0 = __int_as_float(cv0.y), v1 = __int_as_float(cv1.y);
        float v2 = __int_as_float(cv2.y), v3 = __int_as_float(cv3.y);
        a0.x += v0 * x0.x; a0.y += v0 * x0.y; a0.z += v0 * x0.z; a0.w += v0 * x0.w;
        a1.x += v1 * x1.x; a1.y += v1 * x1.y; a1.z += v1 * x1.z; a1.w += v1 * x1.w;
        a2.x += v2 * x2.x; a2.y += v2 * x2.y; a2.z += v2 * x2.z; a2.w += v2 * x2.w;
        a3.x += v3 * x3.x; a3.y += v3 * x3.y; a3.z += v3 * x3.z; a3.w += v3 * x3.w;
    }
    for (; e < end; e++) {
        int2 cv = g_cv[e];
        float4 x = E4[cv.x * 16 + hl];
        float v = __int_as_float(cv.y);
        a0.x += v * x.x; a0.y += v * x.y; a0.z += v * x.z; a0.w += v * x.w;
    }
    a0.x += a1.x + a2.x + a3.x;
    a0.y += a1.y + a2.y + a3.y;
    a0.z += a1.z + a2.z + a3.z;
    a0.w += a1.w + a2.w + a3.w;
    g_LE[row * 16 + hl] = a0;
}

// ================= W split (hi/lo tf32), transposed + padded =================
__global__ void k_wsplit(const float* __restrict__ w1, const float* __restrict__ w2) {
    int idx = blockIdx.x * 256 + threadIdx.x;  // over NLAYER*64*128
    if (idx >= NLAYER * 64 * 128) return;
    int layer = idx / (64 * 128);
    int rem = idx % (64 * 128);
    int n = rem / 128, k = rem % 128;
    float w = (k < 64) ? w1[layer * 4096 + k * 64 + n]
                       : w2[layer * 4096 + (k - 64) * 64 + n];
    unsigned int hi;
    asm("cvt.rna.tf32.f32 %0, %1;" : "=r"(hi) : "f"(w));
    float lof = w - __uint_as_float(hi);
    unsigned int lo;
    asm("cvt.rna.tf32.f32 %0, %1;" : "=r"(lo) : "f"(lof));
    g_whiT[layer * 64 * WPITCH + n * WPITCH + k] = hi;
    g_wloT[layer * 64 * WPITCH + n * WPITCH + k] = lo;
}

// ================= tensor-core GEMM (3xTF32) + bias + leaky, in-place on E ====
// C[150K x 64] = [LE+E | LE*E] @ [w1;w2], one warp per 16 rows, m16n8k8 mma
#define MMA_TF32(C, A0, A1, A2, A3, B0, B1)                                      \
    asm volatile("mma.sync.aligned.m16n8k8.row.col.f32.tf32.tf32.f32 "           \
                 "{%0,%1,%2,%3}, {%4,%5,%6,%7}, {%8,%9}, {%0,%1,%2,%3};"         \
                 : "+f"(C[0]), "+f"(C[1]), "+f"(C[2]), "+f"(C[3])                \
                 : "r"(A0), "r"(A1), "r"(A2), "r"(A3), "r"(B0), "r"(B1))

__global__ void __launch_bounds__(256) k_gemm_mma(int layer,
                                                  const float* __restrict__ b1,
                                                  const float* __restrict__ b2) {
    __shared__ unsigned int whi[64 * WPITCH];
    __shared__ float bs[64];
    int t = threadIdx.x;
    {
        const uint4* s4 = (const uint4*)(g_whiT + layer * 64 * WPITCH);
        uint4* d4 = (uint4*)whi;
        for (int i = t; i < 64 * WPITCH / 4; i += 256) d4[i] = s4[i];
        if (t < 64) bs[t] = b1[t] + b2[t];
    }
    __syncthreads();

    int warp = t >> 5, lane = t & 31;
    int q = lane & 3, g = lane >> 2;
    int base = blockIdx.x * 128 + warp * 16;
    int r0 = base + g, r1 = base + g + 8;
    int r0c = min(r0, N_NODES - 1), r1c = min(r1, N_NODES - 1);
    const float* __restrict__ Ei = (const float*)g_E;
    const float* __restrict__ LE = (const float*)g_LE;
    const unsigned int* __restrict__ wlo = g_wloT + layer * 64 * WPITCH;

    float C[8][4];
#pragma unroll
    for (int i = 0; i < 8; i++)
#pragma unroll
        for (int j = 0; j < 4; j++) C[i][j] = 0.f;

#pragma unroll
    for (int kk = 0; kk < 16; kk++) {
        int half = kk >> 3;            // 0: (LE+E) half, 1: (LE*E) half
        int cb = (kk & 7) * 8;
        int c0 = cb + q, c1 = cb + q + 4;
        float l00 = LE[r0c * 64 + c0], e00 = Ei[r0c * 64 + c0];
        float l10 = LE[r1c * 64 + c0], e10 = Ei[r1c * 64 + c0];
        float l01 = LE[r0c * 64 + c1], e01 = Ei[r0c * 64 + c1];
        float l11 = LE[r1c * 64 + c1], e11 = Ei[r1c * 64 + c1];
        float x0 = half ? l00 * e00 : l00 + e00;
        float x1 = half ? l10 * e10 : l10 + e10;
        float x2 = half ? l01 * e01 : l01 + e01;
        float x3 = half ? l11 * e11 : l11 + e11;
        unsigned int ah0, ah1, ah2, ah3, al0, al1, al2, al3;
        asm("cvt.rna.tf32.f32 %0, %1;" : "=r"(ah0) : "f"(x0));
        asm("cvt.rna.tf32.f32 %0, %1;" : "=r"(ah1) : "f"(x1));
        asm("cvt.rna.tf32.f32 %0, %1;" : "=r"(ah2) : "f"(x2));
        asm("cvt.rna.tf32.f32 %0, %1;" : "=r"(ah3) : "f"(x3));
        float y0 = x0 - __uint_as_float(ah0);
        float y1 = x1 - __uint_as_float(ah1);
        float y2 = x2 - __uint_as_float(ah2);
        float y3 = x3 - __uint_as_float(ah3);
        asm("cvt.rna.tf32.f32 %0, %1;" : "=r"(al0) : "f"(y0));
        asm("cvt.rna.tf32.f32 %0, %1;" : "=r"(al1) : "f"(y1));
        asm("cvt.rna.tf32.f32 %0, %1;" : "=r"(al2) : "f"(y2));
        asm("cvt.rna.tf32.f32 %0, %1;" : "=r"(al3) : "f"(y3));
        int krow = kk * 8 + q;
#pragma unroll
        for (int nt = 0; nt < 8; nt++) {
            int wb = (nt * 8 + g) * WPITCH + krow;
            unsigned int bh0 = whi[wb], bh1 = whi[wb + 4];
            unsigned int bl0 = __ldg(&wlo[wb]), bl1 = __ldg(&wlo[wb + 4]);
            MMA_TF32(C[nt], ah0, ah1, ah2, ah3, bh0, bh1);
            MMA_TF32(C[nt], al0, al1, al2, al3, bh0, bh1);
            MMA_TF32(C[nt], ah0, ah1, ah2, ah3, bl0, bl1);
        }
    }

    float* Eo = (float*)g_E;
#pragma unroll
    for (int nt = 0; nt < 8; nt++) {
        int col = nt * 8 + 2 * q;
        float b0v = bs[col], b1v = bs[col + 1];
        float v00 = C[nt][0] + b0v, v01 = C[nt][1] + b1v;
        float v10 = C[nt][2] + b0v, v11 = C[nt][3] + b1v;
        v00 = v00 >= 0.f ? v00 : 0.2f * v00;
        v01 = v01 >= 0.f ? v01 : 0.2f * v01;
        v10 = v10 >= 0.f ? v10 : 0.2f * v10;
        v11 = v11 >= 0.f ? v11 : 0.2f * v11;
        if (r0 < N_NODES) *(float2*)(Eo + r0 * 64 + col) = make_float2(v00, v01);
        if (r1 < N_NODES) *(float2*)(Eo + r1 * 64 + col) = make_float2(v10, v11);
    }
}

// ---------------- gather (with optional row-normalize) into output ----------------
__global__ void k_gather(const int* __restrict__ user_idx, const int* __restrict__ pos_idx,
                         const int* __restrict__ neg_idx, float* __restrict__ out, int layer) {
    int w = (blockIdx.x * blockDim.x + threadIdx.x) >> 5;
    int lane = threadIdx.x & 31;
    if (w >= 3 * BB) return;
    int node;
    if (w < BB)          node = user_idx[w];
    else if (w < 2 * BB) node = N_USER + pos_idx[w - BB];
    else                 node = N_USER + neg_idx[w - 2 * BB];
    float2 v = ((const float2*)g_E)[node * 32 + lane];
    float scale = 1.0f;
    if (layer > 0) {
        float s = v.x * v.x + v.y * v.y;
#pragma unroll
        for (int o = 16; o; o >>= 1) s += __shfl_xor_sync(0xffffffffu, s, o);
        scale = 1.0f / fmaxf(sqrtf(s), 1e-12f);
    }
    ((float2*)(out + (size_t)w * 256 + layer * 64))[lane] = make_float2(v.x * scale, v.y * scale);
}

extern "C" void kernel_launch(void* const* d_in, const int* in_sizes, int n_in,
                              void* d_out, int out_size) {
    const float *user_emb, *item_emb, *lin1_w, *lin1_b, *lin2_w, *lin2_b;
    const float *w1, *b1, *w2, *b2, *lap_val, *user_feat, *mlp_ratio;
    const int *lap_row, *lap_col, *user_idx, *pos_idx, *neg_idx;

    if (in_sizes[2] == 4096) {
        user_emb = (const float*)d_in[0];  item_emb = (const float*)d_in[1];
        user_feat= (const float*)d_in[2];
        lin1_w   = (const float*)d_in[3];  lin1_b   = (const float*)d_in[4];
        lin2_w   = (const float*)d_in[5];  lin2_b   = (const float*)d_in[6];
        w1 = (const float*)d_in[7];  b1 = (const float*)d_in[8];
        w2 = (const float*)d_in[9];  b2 = (const float*)d_in[10];
        lap_val  = (const float*)d_in[11]; mlp_ratio = (const float*)d_in[12];
        lap_row  = (const int*)d_in[13];   lap_col   = (const int*)d_in[14];
        user_idx = (const int*)d_in[15];   pos_idx   = (const int*)d_in[16];
        neg_idx  = (const int*)d_in[17];
    } else {
        user_emb = (const float*)d_in[0];  item_emb = (const float*)d_in[1];
        lin1_w   = (const float*)d_in[2];  lin1_b   = (const float*)d_in[3];
        lin2_w   = (const float*)d_in[4];  lin2_b   = (const float*)d_in[5];
        w1 = (const float*)d_in[6];  b1 = (const float*)d_in[7];
        w2 = (const float*)d_in[8];  b2 = (const float*)d_in[9];
        lap_row  = (const int*)d_in[10];   lap_col  = (const int*)d_in[11];
        lap_val  = (const float*)d_in[12];
        user_idx = (const int*)d_in[13];   user_feat = (const float*)d_in[14];
        pos_idx  = (const int*)d_in[15];   neg_idx   = (const int*)d_in[16];
        mlp_ratio= (const float*)d_in[17];
    }

    float* out = (float*)d_out;
    const int V4 = N_NODES * 16;

    // CSR build + weight split (independent of E; do them first)
    k_cnt_zero<<<NB_SCAN, 256>>>();
    k_hist<<<(NNZ + 255) / 256, 256>>>(lap_row);
    k_scan1<<<NB_SCAN, 256>>>();
    k_scan2<<<1, 1024>>>();
    k_scan3<<<NB_SCAN, 256>>>();
    k_fill<<<(NNZ + 255) / 256, 256>>>(lap_row, lap_col, lap_val);
    k_wsplit<<<(NLAYER * 64 * 128 + 255) / 256, 256>>>(w1, w2);

    k_mlp<<<BB, 64>>>(user_feat, lin1_w, lin1_b, lin2_w, lin2_b);
    k_init<<<(V4 + 255) / 256, 256>>>((const float4*)user_emb, (const float4*)item_emb);
    k_win_reset<<<(BB + 255) / 256, 256>>>(user_idx);
    k_win_max<<<(BB + 255) / 256, 256>>>(user_idx);
    k_apply<<<BB, 64>>>(user_idx, user_emb, mlp_ratio);
    k_gather<<<(3 * BB * 32 + 255) / 256, 256>>>(user_idx, pos_idx, neg_idx, out, 0);

    for (int k = 0; k < NLAYER; k++) {
        // 2 rows per warp -> N_NODES/2 warps -> /8 warps per block
        k_spmm_csr<<<(N_NODES / 2 + 7) / 8, 256>>>();
        k_gemm_mma<<<(N_NODES + 127) / 128, 256>>>(k, b1 + k * 64, b2 + k * 64);
        k_gather<<<(3 * BB * 32 + 255) / 256, 256>>>(user_idx, pos_idx, neg_idx, out, k + 1);
    }
}